// round 2
// baseline (speedup 1.0000x reference)
#include <cuda_runtime.h>
#include <cstdint>
#include <cstddef>

// ---------------------------------------------------------------------------
// GATEncoder: GATConv(2000->4x512, mean heads) -> BN -> ELU -> GATConv(512->30)
// N=50000, F=2000, H=4, C=512, LAT=30, E=800000 (+N self loops)
// ---------------------------------------------------------------------------

#define NMAX 50000
#define EMAX 800000
#define ETMAX (EMAX + NMAX)

// ---- device scratch (static; no runtime allocation allowed) ----
__device__ float    g_H1[(size_t)NMAX * 2048];    // x @ W1            409.6 MB
__device__ float    g_out1[(size_t)NMAX * 512];   // layer-1 aggregate 102.4 MB
__device__ float    g_hmid[(size_t)NMAX * 512];   // after BN+ELU      102.4 MB
__device__ float    g_H2[(size_t)NMAX * 30];      // hmid @ W2
__device__ float    g_asrc1[NMAX * 4];
__device__ float    g_adst1[NMAX * 4];
__device__ unsigned g_max1[NMAX * 4];
__device__ float    g_sum1[NMAX * 4];
__device__ float    g_e1[(size_t)ETMAX * 4];
__device__ float    g_asrc2[NMAX];
__device__ float    g_adst2[NMAX];
__device__ unsigned g_max2[NMAX];
__device__ float    g_sum2[NMAX];
__device__ float    g_e2[ETMAX];
__device__ float    g_stats[1024];                // [0:512) sum, [512:1024) sumsq

// ---- helpers ----
__device__ __forceinline__ float tf32_rne(float x) {
    float r; asm("cvt.rna.tf32.f32 %0, %1;" : "=f"(r) : "f"(x)); return r;
}
__device__ __forceinline__ unsigned f2ord(float f) {
    unsigned u = __float_as_uint(f);
    return (u & 0x80000000u) ? ~u : (u | 0x80000000u);
}
__device__ __forceinline__ float ord2f(unsigned u) {
    unsigned b = (u & 0x80000000u) ? (u & 0x7FFFFFFFu) : ~u;
    return __uint_as_float(b);
}
__device__ __forceinline__ float lrelu(float v) { return v > 0.f ? v : 0.2f * v; }

// ---------------------------------------------------------------------------
// init: zero accumulators, seed segment-max with ordered(-inf)<=0, out = b2
// ---------------------------------------------------------------------------
__global__ void k_init(float* __restrict__ out, const float* __restrict__ b2, int Nn) {
    size_t total = (size_t)Nn * 512;
    for (size_t i = (size_t)blockIdx.x * blockDim.x + threadIdx.x; i < total;
         i += (size_t)gridDim.x * blockDim.x) {
        g_out1[i] = 0.f;
        if (i < (size_t)Nn * 4) { g_sum1[i] = 0.f; g_max1[i] = 0u; }
        if (i < (size_t)Nn)     { g_sum2[i] = 0.f; g_max2[i] = 0u; }
        if (i < 1024)           { g_stats[i] = 0.f; }
        if (i < (size_t)Nn * 30) out[i] = b2[i % 30];
    }
}

// ---------------------------------------------------------------------------
// GEMM1: g_H1[M,2048] = A[M,2000] @ B[2000,2048], tf32 mma.m16n8k8
// BM=128 BN=128 BK=16, 256 thr = 8 warps (4m x 2n), warp tile 32x64
// ---------------------------------------------------------------------------
__global__ __launch_bounds__(256, 2)
void k_gemm1(const float* __restrict__ A, const float* __restrict__ B, int M) {
    __shared__ float As[128][20];   // pad 20 -> conflict-free A-fragment reads
    __shared__ float Bs[16][136];   // pad 136 -> conflict-free B-frag reads, 16B-aligned f4 stores
    const int tid  = threadIdx.x;
    const int lane = tid & 31, warp = tid >> 5;
    const int gid  = lane >> 2, tig = lane & 3;
    const int wm   = warp >> 1, wn = warp & 1;
    const int rowBase = blockIdx.y * 128;
    const int colBase = blockIdx.x * 128;

    float acc[2][8][4];
#pragma unroll
    for (int i = 0; i < 2; i++)
#pragma unroll
        for (int j = 0; j < 8; j++)
#pragma unroll
            for (int k = 0; k < 4; k++) acc[i][j][k] = 0.f;

    for (int k0 = 0; k0 < 2000; k0 += 16) {
        // A tile: 128x16, 512 float4, 2 per thread
#pragma unroll
        for (int i = 0; i < 2; i++) {
            int idx = tid + i * 256;
            int r = idx >> 2;
            int cg = (idx & 3) * 4;
            float4 v = make_float4(0.f, 0.f, 0.f, 0.f);
            int gr = rowBase + r;
            if (gr < M) v = __ldg((const float4*)(A + (size_t)gr * 2000 + k0 + cg));
            As[r][cg + 0] = tf32_rne(v.x);
            As[r][cg + 1] = tf32_rne(v.y);
            As[r][cg + 2] = tf32_rne(v.z);
            As[r][cg + 3] = tf32_rne(v.w);
        }
        // B tile: 16x128
#pragma unroll
        for (int i = 0; i < 2; i++) {
            int idx = tid + i * 256;
            int r = idx >> 5;
            int cg = (idx & 31) * 4;
            float4 v = __ldg((const float4*)(B + (size_t)(k0 + r) * 2048 + colBase + cg));
            float4 t = make_float4(tf32_rne(v.x), tf32_rne(v.y), tf32_rne(v.z), tf32_rne(v.w));
            *(float4*)&Bs[r][cg] = t;
        }
        __syncthreads();
#pragma unroll
        for (int ks = 0; ks < 2; ks++) {
            unsigned a[2][4], b[8][2];
#pragma unroll
            for (int tm = 0; tm < 2; tm++) {
                int r = wm * 32 + tm * 16;
                int kk = ks * 8 + tig;
                a[tm][0] = __float_as_uint(As[r + gid][kk]);
                a[tm][1] = __float_as_uint(As[r + gid + 8][kk]);
                a[tm][2] = __float_as_uint(As[r + gid][kk + 4]);
                a[tm][3] = __float_as_uint(As[r + gid + 8][kk + 4]);
            }
#pragma unroll
            for (int tn = 0; tn < 8; tn++) {
                int c = wn * 64 + tn * 8 + gid;
                b[tn][0] = __float_as_uint(Bs[ks * 8 + tig][c]);
                b[tn][1] = __float_as_uint(Bs[ks * 8 + tig + 4][c]);
            }
#pragma unroll
            for (int tm = 0; tm < 2; tm++)
#pragma unroll
                for (int tn = 0; tn < 8; tn++) {
                    asm volatile(
                        "mma.sync.aligned.m16n8k8.row.col.f32.tf32.tf32.f32 "
                        "{%0,%1,%2,%3},{%4,%5,%6,%7},{%8,%9},{%0,%1,%2,%3};\n"
                        : "+f"(acc[tm][tn][0]), "+f"(acc[tm][tn][1]),
                          "+f"(acc[tm][tn][2]), "+f"(acc[tm][tn][3])
                        : "r"(a[tm][0]), "r"(a[tm][1]), "r"(a[tm][2]), "r"(a[tm][3]),
                          "r"(b[tn][0]), "r"(b[tn][1]));
                }
        }
        __syncthreads();
    }
    // epilogue
#pragma unroll
    for (int tm = 0; tm < 2; tm++) {
        int r0 = rowBase + wm * 32 + tm * 16 + gid;
#pragma unroll
        for (int tn = 0; tn < 8; tn++) {
            int c = colBase + wn * 64 + tn * 8 + tig * 2;
            if (r0 < M) {
                g_H1[(size_t)r0 * 2048 + c]     = acc[tm][tn][0];
                g_H1[(size_t)r0 * 2048 + c + 1] = acc[tm][tn][1];
            }
            if (r0 + 8 < M) {
                g_H1[(size_t)(r0 + 8) * 2048 + c]     = acc[tm][tn][2];
                g_H1[(size_t)(r0 + 8) * 2048 + c + 1] = acc[tm][tn][3];
            }
        }
    }
}

// ---------------------------------------------------------------------------
// attention dots layer 1: a_src/a_dst[n,h] = <H1[n,h,:], att[h,:]> (one warp per (n,h))
// ---------------------------------------------------------------------------
__global__ void k_att1(const float* __restrict__ att_src, const float* __restrict__ att_dst,
                       int Nn) {
    int gw = (int)(((size_t)blockIdx.x * blockDim.x + threadIdx.x) >> 5);
    int lane = threadIdx.x & 31;
    if (gw >= Nn * 4) return;
    int n = gw >> 2, h = gw & 3;
    const float4* r4 = (const float4*)(g_H1 + (size_t)n * 2048 + h * 512);
    const float4* s4 = (const float4*)(att_src + h * 512);
    const float4* d4 = (const float4*)(att_dst + h * 512);
    float ss = 0.f, dd = 0.f;
#pragma unroll 4
    for (int i = lane; i < 128; i += 32) {
        float4 v = r4[i], a = s4[i], b = d4[i];
        ss += v.x * a.x + v.y * a.y + v.z * a.z + v.w * a.w;
        dd += v.x * b.x + v.y * b.y + v.z * b.z + v.w * b.w;
    }
#pragma unroll
    for (int off = 16; off; off >>= 1) {
        ss += __shfl_down_sync(0xffffffffu, ss, off);
        dd += __shfl_down_sync(0xffffffffu, dd, off);
    }
    if (lane == 0) { g_asrc1[gw] = ss; g_adst1[gw] = dd; }
}

// ---------------------------------------------------------------------------
// layer-1 edge passes
// ---------------------------------------------------------------------------
__global__ void k_edge_max1(const int* __restrict__ ei, int E, int Nn) {
    int e = blockIdx.x * blockDim.x + threadIdx.x;
    if (e >= E + Nn) return;
    int s, d;
    if (e < E) { s = ei[e]; d = ei[E + e]; } else { s = d = e - E; }
    float4 as = *(const float4*)(g_asrc1 + (size_t)s * 4);
    float4 ad = *(const float4*)(g_adst1 + (size_t)d * 4);
    float4 ev = make_float4(lrelu(as.x + ad.x), lrelu(as.y + ad.y),
                            lrelu(as.z + ad.z), lrelu(as.w + ad.w));
    *(float4*)(g_e1 + (size_t)e * 4) = ev;
    atomicMax(&g_max1[d * 4 + 0], f2ord(ev.x));
    atomicMax(&g_max1[d * 4 + 1], f2ord(ev.y));
    atomicMax(&g_max1[d * 4 + 2], f2ord(ev.z));
    atomicMax(&g_max1[d * 4 + 3], f2ord(ev.w));
}

__global__ void k_exp1(const int* __restrict__ ei, int E, int Nn) {
    int e = blockIdx.x * blockDim.x + threadIdx.x;
    if (e >= E + Nn) return;
    int d = (e < E) ? ei[E + e] : e - E;
    float4 ev = *(const float4*)(g_e1 + (size_t)e * 4);
    ev.x = expf(ev.x - ord2f(g_max1[d * 4 + 0]));
    ev.y = expf(ev.y - ord2f(g_max1[d * 4 + 1]));
    ev.z = expf(ev.z - ord2f(g_max1[d * 4 + 2]));
    ev.w = expf(ev.w - ord2f(g_max1[d * 4 + 3]));
    *(float4*)(g_e1 + (size_t)e * 4) = ev;
    atomicAdd(&g_sum1[d * 4 + 0], ev.x);
    atomicAdd(&g_sum1[d * 4 + 1], ev.y);
    atomicAdd(&g_sum1[d * 4 + 2], ev.z);
    atomicAdd(&g_sum1[d * 4 + 3], ev.w);
}

// one warp per edge; head-mean fused (x0.25); accumulate [N,512]
__global__ void k_msg1(const int* __restrict__ ei, int E, int Nn) {
    int gw = (int)(((size_t)blockIdx.x * blockDim.x + threadIdx.x) >> 5);
    int lane = threadIdx.x & 31;
    if (gw >= E + Nn) return;
    int s, d;
    if (gw < E) { s = ei[gw]; d = ei[E + gw]; } else { s = d = gw - E; }
    float4 ex = *(const float4*)(g_e1 + (size_t)gw * 4);
    float4 sm = *(const float4*)(g_sum1 + (size_t)d * 4);
    float a0 = ex.x / (sm.x + 1e-16f) * 0.25f;
    float a1 = ex.y / (sm.y + 1e-16f) * 0.25f;
    float a2 = ex.z / (sm.z + 1e-16f) * 0.25f;
    float a3 = ex.w / (sm.w + 1e-16f) * 0.25f;
    const float4* h0 = (const float4*)(g_H1 + (size_t)s * 2048);
    const float4* h1 = h0 + 128;
    const float4* h2 = h0 + 256;
    const float4* h3 = h0 + 384;
    float* orow = g_out1 + (size_t)d * 512;
#pragma unroll
    for (int c4 = lane; c4 < 128; c4 += 32) {
        float4 v0 = __ldg(h0 + c4), v1 = __ldg(h1 + c4), v2 = __ldg(h2 + c4), v3 = __ldg(h3 + c4);
        float rx = a0 * v0.x + a1 * v1.x + a2 * v2.x + a3 * v3.x;
        float ry = a0 * v0.y + a1 * v1.y + a2 * v2.y + a3 * v3.y;
        float rz = a0 * v0.z + a1 * v1.z + a2 * v2.z + a3 * v3.z;
        float rw = a0 * v0.w + a1 * v1.w + a2 * v2.w + a3 * v3.w;
        atomicAdd(orow + c4 * 4 + 0, rx);
        atomicAdd(orow + c4 * 4 + 1, ry);
        atomicAdd(orow + c4 * 4 + 2, rz);
        atomicAdd(orow + c4 * 4 + 3, rw);
    }
}

// ---------------------------------------------------------------------------
// BatchNorm stats (b1 is BN-invariant -> skipped) + normalize + ELU
// ---------------------------------------------------------------------------
__global__ void k_bnstats(int Nn) {
    int c = blockIdx.x * blockDim.x + threadIdx.x;   // 0..511 (grid.x=2)
    int r0 = blockIdx.y * 64;
    int r1 = min(r0 + 64, Nn);
    float s1 = 0.f, s2 = 0.f;
    for (int r = r0; r < r1; r++) {
        float v = g_out1[(size_t)r * 512 + c];
        s1 += v;
        s2 = fmaf(v, v, s2);
    }
    atomicAdd(&g_stats[c], s1);
    atomicAdd(&g_stats[512 + c], s2);
}

__global__ void k_bnelu(const float* __restrict__ gamma, const float* __restrict__ beta,
                        int Nn, float invN) {
    size_t total = (size_t)Nn * 512;
    for (size_t i = (size_t)blockIdx.x * blockDim.x + threadIdx.x; i < total;
         i += (size_t)gridDim.x * blockDim.x) {
        int c = (int)(i & 511);
        float mu = g_stats[c] * invN;
        float var = g_stats[512 + c] * invN - mu * mu;
        float x = (g_out1[i] - mu) * rsqrtf(var + 1e-5f) * gamma[c] + beta[c];
        g_hmid[i] = x > 0.f ? x : expm1f(x);
    }
}

// ---------------------------------------------------------------------------
// layer-2 prep: H2 = hmid @ W2 (one warp per row) + attention scalars
// ---------------------------------------------------------------------------
__global__ void k_l2prep(const float* __restrict__ W2, const float* __restrict__ as2,
                         const float* __restrict__ ad2, int Nn) {
    int gw = (int)(((size_t)blockIdx.x * blockDim.x + threadIdx.x) >> 5);
    int lane = threadIdx.x & 31;
    if (gw >= Nn) return;
    const float* h = g_hmid + (size_t)gw * 512;
    float acc = 0.f;
    for (int kb = 0; kb < 16; kb++) {
        float hv = h[kb * 32 + lane];
#pragma unroll
        for (int j = 0; j < 32; j++) {
            float hk = __shfl_sync(0xffffffffu, hv, j);
            float w = (lane < 30) ? __ldg(W2 + (size_t)(kb * 32 + j) * 30 + lane) : 0.f;
            acc = fmaf(hk, w, acc);
        }
    }
    float sa = (lane < 30) ? acc * __ldg(as2 + lane) : 0.f;
    float sd = (lane < 30) ? acc * __ldg(ad2 + lane) : 0.f;
#pragma unroll
    for (int off = 16; off; off >>= 1) {
        sa += __shfl_down_sync(0xffffffffu, sa, off);
        sd += __shfl_down_sync(0xffffffffu, sd, off);
    }
    if (lane < 30) g_H2[(size_t)gw * 30 + lane] = acc;
    if (lane == 0) { g_asrc2[gw] = sa; g_adst2[gw] = sd; }
}

// ---------------------------------------------------------------------------
// layer-2 edge passes (H=1, C=30)
// ---------------------------------------------------------------------------
__global__ void k_edge_max2(const int* __restrict__ ei, int E, int Nn) {
    int e = blockIdx.x * blockDim.x + threadIdx.x;
    if (e >= E + Nn) return;
    int s, d;
    if (e < E) { s = ei[e]; d = ei[E + e]; } else { s = d = e - E; }
    float v = lrelu(g_asrc2[s] + g_adst2[d]);
    g_e2[e] = v;
    atomicMax(&g_max2[d], f2ord(v));
}

__global__ void k_exp2(const int* __restrict__ ei, int E, int Nn) {
    int e = blockIdx.x * blockDim.x + threadIdx.x;
    if (e >= E + Nn) return;
    int d = (e < E) ? ei[E + e] : e - E;
    float ex = expf(g_e2[e] - ord2f(g_max2[d]));
    g_e2[e] = ex;
    atomicAdd(&g_sum2[d], ex);
}

__global__ void k_msg2(const int* __restrict__ ei, int E, int Nn, float* __restrict__ out) {
    int gw = (int)(((size_t)blockIdx.x * blockDim.x + threadIdx.x) >> 5);
    int lane = threadIdx.x & 31;
    if (gw >= E + Nn) return;
    int s, d;
    if (gw < E) { s = ei[gw]; d = ei[E + gw]; } else { s = d = gw - E; }
    float al = g_e2[gw] / (g_sum2[d] + 1e-16f);
    if (lane < 30)
        atomicAdd(out + (size_t)d * 30 + lane, al * __ldg(g_H2 + (size_t)s * 30 + lane));
}

// ---------------------------------------------------------------------------
// launch
// ---------------------------------------------------------------------------
extern "C" void kernel_launch(void* const* d_in, const int* in_sizes, int n_in,
                              void* d_out, int out_size) {
    const float* x       = (const float*)d_in[0];
    const int*   ei      = (const int*)d_in[1];
    const float* W1      = (const float*)d_in[2];
    const float* attsrc1 = (const float*)d_in[3];
    const float* attdst1 = (const float*)d_in[4];
    // d_in[5] = b1: provably BN-invariant, skipped
    const float* gamma   = (const float*)d_in[6];
    const float* beta    = (const float*)d_in[7];
    const float* W2      = (const float*)d_in[8];
    const float* attsrc2 = (const float*)d_in[9];
    const float* attdst2 = (const float*)d_in[10];
    const float* b2      = (const float*)d_in[11];
    float* out = (float*)d_out;

    int Nn = in_sizes[0] / 2000;
    int E  = in_sizes[1] / 2;
    int Etot = E + Nn;

    k_init<<<2048, 256>>>(out, b2, Nn);

    dim3 g1(2048 / 128, (Nn + 127) / 128);
    k_gemm1<<<g1, 256>>>(x, W1, Nn);

    k_att1<<<(Nn * 4 * 32 + 255) / 256, 256>>>(attsrc1, attdst1, Nn);

    int eb = (Etot + 255) / 256;
    k_edge_max1<<<eb, 256>>>(ei, E, Nn);
    k_exp1<<<eb, 256>>>(ei, E, Nn);

    int mb = (int)(((size_t)Etot * 32 + 255) / 256);
    k_msg1<<<mb, 256>>>(ei, E, Nn);

    dim3 gs(2, (Nn + 63) / 64);
    k_bnstats<<<gs, 256>>>(Nn);
    k_bnelu<<<4096, 256>>>(gamma, beta, Nn, 1.f / (float)Nn);

    k_l2prep<<<(int)(((size_t)Nn * 32 + 255) / 256), 256>>>(W2, attsrc2, attdst2, Nn);

    k_edge_max2<<<eb, 256>>>(ei, E, Nn);
    k_exp2<<<eb, 256>>>(ei, E, Nn);
    k_msg2<<<mb, 256>>>(ei, E, Nn, out);
}

// round 3
// speedup vs baseline: 1.3543x; 1.3543x over previous
#include <cuda_runtime.h>
#include <cstdint>
#include <cstddef>

// ---------------------------------------------------------------------------
// GATEncoder: GATConv(2000->4x512, mean heads) -> BN -> ELU -> GATConv(512->30)
// N=50000, F=2000, H=4, C=512, LAT=30, E=800000 (+N self loops)
// R3: cp.async-pipelined tf32 GEMM1 + CSR-fused layer-1 softmax/aggregation
// ---------------------------------------------------------------------------

#define NMAX 50000
#define EMAX 800000
#define ETMAX (EMAX + NMAX)
#define GEMM_STAGES 4
#define AS_STRIDE 20
#define BS_STRIDE 136
#define AS_TILE (128 * AS_STRIDE)
#define BS_TILE (16 * BS_STRIDE)
#define SMEM_GEMM (GEMM_STAGES * (AS_TILE + BS_TILE) * 4)

// ---- device scratch (static; no runtime allocation allowed) ----
__device__ float    g_H1[(size_t)NMAX * 2048];    // x @ W1
__device__ float    g_out1[(size_t)NMAX * 512];   // layer-1 aggregate
__device__ float    g_hmid[(size_t)NMAX * 512];   // after BN+ELU
__device__ float    g_H2[(size_t)NMAX * 30];      // hmid @ W2
__device__ float    g_asrc1[NMAX * 4];
__device__ float    g_adst1[NMAX * 4];
__device__ float    g_asrc2[NMAX];
__device__ float    g_adst2[NMAX];
__device__ unsigned g_max2[NMAX];
__device__ float    g_sum2[NMAX];
__device__ float    g_e2[ETMAX];
__device__ float    g_stats[1024];                // [0:512) sum, [512:1024) sumsq
// CSR by destination
__device__ int      g_deg[NMAX];
__device__ int      g_rowptr[NMAX + 1];
__device__ int      g_woff[NMAX];
__device__ int      g_csr_src[ETMAX];

// ---- helpers ----
__device__ __forceinline__ float tf32_rne(float x) {
    float r; asm("cvt.rna.tf32.f32 %0, %1;" : "=f"(r) : "f"(x)); return r;
}
__device__ __forceinline__ unsigned f2ord(float f) {
    unsigned u = __float_as_uint(f);
    return (u & 0x80000000u) ? ~u : (u | 0x80000000u);
}
__device__ __forceinline__ float ord2f(unsigned u) {
    unsigned b = (u & 0x80000000u) ? (u & 0x7FFFFFFFu) : ~u;
    return __uint_as_float(b);
}
__device__ __forceinline__ float lrelu(float v) { return v > 0.f ? v : 0.2f * v; }

__device__ __forceinline__ void cp16(void* sptr, const void* gptr, bool pred) {
    unsigned saddr = (unsigned)__cvta_generic_to_shared(sptr);
    int sz = pred ? 16 : 0;
    asm volatile("cp.async.cg.shared.global [%0], [%1], 16, %2;\n"
                 :: "r"(saddr), "l"(gptr), "r"(sz));
}
__device__ __forceinline__ void cp_commit() {
    asm volatile("cp.async.commit_group;\n" ::: "memory");
}
__device__ __forceinline__ void cp_wait2() {
    asm volatile("cp.async.wait_group %0;\n" :: "n"(GEMM_STAGES - 2) : "memory");
}

// ---------------------------------------------------------------------------
// init: zero CSR degree + layer2 accumulators + stats; out = b2
// ---------------------------------------------------------------------------
__global__ void k_init(float* __restrict__ out, const float* __restrict__ b2, int Nn) {
    size_t total = (size_t)Nn * 30;
    for (size_t i = (size_t)blockIdx.x * blockDim.x + threadIdx.x; i < total;
         i += (size_t)gridDim.x * blockDim.x) {
        if (i < (size_t)Nn) { g_deg[i] = 0; g_sum2[i] = 0.f; g_max2[i] = 0u; }
        if (i < 1024) g_stats[i] = 0.f;
        out[i] = b2[i % 30];
    }
}

// ---------------------------------------------------------------------------
// CSR build: degree count -> exclusive scan -> scatter (src indices)
// ---------------------------------------------------------------------------
__global__ void k_deg(const int* __restrict__ ei, int E, int Nn) {
    int e = blockIdx.x * blockDim.x + threadIdx.x;
    if (e >= E + Nn) return;
    int d = (e < E) ? ei[E + e] : e - E;
    atomicAdd(&g_deg[d], 1);
}

__global__ void k_scan(int Nn) {
    __shared__ int wsum[32];
    __shared__ int carry_s;
    int tid = threadIdx.x;
    if (tid == 0) carry_s = 0;
    __syncthreads();
    int iters = (Nn + 1023) / 1024;
    for (int it = 0; it < iters; it++) {
        int i = it * 1024 + tid;
        int v = (i < Nn) ? g_deg[i] : 0;
        int x = v;
#pragma unroll
        for (int o = 1; o < 32; o <<= 1) {
            int y = __shfl_up_sync(0xffffffffu, x, o);
            if ((tid & 31) >= o) x += y;
        }
        if ((tid & 31) == 31) wsum[tid >> 5] = x;
        __syncthreads();
        if (tid < 32) {
            int w = wsum[tid];
#pragma unroll
            for (int o = 1; o < 32; o <<= 1) {
                int y = __shfl_up_sync(0xffffffffu, w, o);
                if (tid >= o) w += y;
            }
            wsum[tid] = w;
        }
        __syncthreads();
        int warp = tid >> 5;
        int incl = x + (warp ? wsum[warp - 1] : 0);
        int excl = incl - v;
        int c = carry_s;
        if (i < Nn) { g_rowptr[i] = c + excl; g_woff[i] = c + excl; }
        __syncthreads();
        if (tid == 1023) carry_s = c + incl;
        __syncthreads();
    }
    if (tid == 0) g_rowptr[Nn] = carry_s;
}

__global__ void k_scatter(const int* __restrict__ ei, int E, int Nn) {
    int e = blockIdx.x * blockDim.x + threadIdx.x;
    if (e >= E + Nn) return;
    int s, d;
    if (e < E) { s = ei[e]; d = ei[E + e]; } else { s = d = e - E; }
    int pos = atomicAdd(&g_woff[d], 1);
    g_csr_src[pos] = s;
}

// ---------------------------------------------------------------------------
// GEMM1: g_H1[M,2048] = A[M,2000] @ B[2000,2048], tf32 mma.m16n8k8
// BM=128 BN=128 BK=16, 4-stage cp.async pipeline, 256 thr (4m x 2n warps)
// ---------------------------------------------------------------------------
__global__ __launch_bounds__(256, 2)
void k_gemm1(const float* __restrict__ A, const float* __restrict__ B, int M) {
    extern __shared__ float smem[];
    float* AsBase = smem;                                // [S][128*20]
    float* BsBase = smem + GEMM_STAGES * AS_TILE;        // [S][16*136]

    const int tid  = threadIdx.x;
    const int lane = tid & 31, warp = tid >> 5;
    const int gid  = lane >> 2, tig = lane & 3;
    const int wm   = warp >> 1, wn = warp & 1;
    const int rowBase = blockIdx.y * 128;
    const int colBase = blockIdx.x * 128;
    const int KITERS = 125;   // 2000 / 16

    float acc[2][8][4];
#pragma unroll
    for (int i = 0; i < 2; i++)
#pragma unroll
        for (int j = 0; j < 8; j++)
#pragma unroll
            for (int k = 0; k < 4; k++) acc[i][j][k] = 0.f;

    // tile loader
    auto load_tile = [&](int st, int k0) {
        float* As = AsBase + st * AS_TILE;
        float* Bs = BsBase + st * BS_TILE;
#pragma unroll
        for (int i = 0; i < 2; i++) {
            int idx = tid + i * 256;
            int r = idx >> 2;
            int cg = (idx & 3) * 4;
            int gr = rowBase + r;
            cp16(&As[r * AS_STRIDE + cg], A + (size_t)gr * 2000 + k0 + cg, gr < M);
        }
#pragma unroll
        for (int i = 0; i < 2; i++) {
            int idx = tid + i * 256;
            int r = idx >> 5;
            int cg = (idx & 31) * 4;
            cp16(&Bs[r * BS_STRIDE + cg], B + (size_t)(k0 + r) * 2048 + colBase + cg, true);
        }
    };

    // prologue: fill STAGES-1 stages
#pragma unroll
    for (int s = 0; s < GEMM_STAGES - 1; s++) {
        load_tile(s, s * 16);
        cp_commit();
    }

    for (int it = 0; it < KITERS; it++) {
        cp_wait2();
        __syncthreads();
        int st = it % GEMM_STAGES;
        float* As = AsBase + st * AS_TILE;
        float* Bs = BsBase + st * BS_TILE;
#pragma unroll
        for (int ks = 0; ks < 2; ks++) {
            unsigned a[2][4], b[8][2];
#pragma unroll
            for (int tm = 0; tm < 2; tm++) {
                int r = wm * 32 + tm * 16;
                int kk = ks * 8 + tig;
                a[tm][0] = __float_as_uint(tf32_rne(As[(r + gid) * AS_STRIDE + kk]));
                a[tm][1] = __float_as_uint(tf32_rne(As[(r + gid + 8) * AS_STRIDE + kk]));
                a[tm][2] = __float_as_uint(tf32_rne(As[(r + gid) * AS_STRIDE + kk + 4]));
                a[tm][3] = __float_as_uint(tf32_rne(As[(r + gid + 8) * AS_STRIDE + kk + 4]));
            }
#pragma unroll
            for (int tn = 0; tn < 8; tn++) {
                int c = wn * 64 + tn * 8 + gid;
                b[tn][0] = __float_as_uint(tf32_rne(Bs[(ks * 8 + tig) * BS_STRIDE + c]));
                b[tn][1] = __float_as_uint(tf32_rne(Bs[(ks * 8 + tig + 4) * BS_STRIDE + c]));
            }
#pragma unroll
            for (int tm = 0; tm < 2; tm++)
#pragma unroll
                for (int tn = 0; tn < 8; tn++) {
                    asm volatile(
                        "mma.sync.aligned.m16n8k8.row.col.f32.tf32.tf32.f32 "
                        "{%0,%1,%2,%3},{%4,%5,%6,%7},{%8,%9},{%0,%1,%2,%3};\n"
                        : "+f"(acc[tm][tn][0]), "+f"(acc[tm][tn][1]),
                          "+f"(acc[tm][tn][2]), "+f"(acc[tm][tn][3])
                        : "r"(a[tm][0]), "r"(a[tm][1]), "r"(a[tm][2]), "r"(a[tm][3]),
                          "r"(b[tn][0]), "r"(b[tn][1]));
                }
        }
        int nit = it + GEMM_STAGES - 1;
        if (nit < KITERS) load_tile(nit % GEMM_STAGES, nit * 16);
        cp_commit();
    }

    // epilogue
#pragma unroll
    for (int tm = 0; tm < 2; tm++) {
        int r0 = rowBase + wm * 32 + tm * 16 + gid;
#pragma unroll
        for (int tn = 0; tn < 8; tn++) {
            int c = colBase + wn * 64 + tn * 8 + tig * 2;
            if (r0 < M) {
                g_H1[(size_t)r0 * 2048 + c]     = acc[tm][tn][0];
                g_H1[(size_t)r0 * 2048 + c + 1] = acc[tm][tn][1];
            }
            if (r0 + 8 < M) {
                g_H1[(size_t)(r0 + 8) * 2048 + c]     = acc[tm][tn][2];
                g_H1[(size_t)(r0 + 8) * 2048 + c + 1] = acc[tm][tn][3];
            }
        }
    }
}

// ---------------------------------------------------------------------------
// attention dots layer 1: a_src/a_dst[n,h] = <H1[n,h,:], att[h,:]>
// ---------------------------------------------------------------------------
__global__ void k_att1(const float* __restrict__ att_src, const float* __restrict__ att_dst,
                       int Nn) {
    int gw = (int)(((size_t)blockIdx.x * blockDim.x + threadIdx.x) >> 5);
    int lane = threadIdx.x & 31;
    if (gw >= Nn * 4) return;
    int n = gw >> 2, h = gw & 3;
    const float4* r4 = (const float4*)(g_H1 + (size_t)n * 2048 + h * 512);
    const float4* s4 = (const float4*)(att_src + h * 512);
    const float4* d4 = (const float4*)(att_dst + h * 512);
    float ss = 0.f, dd = 0.f;
#pragma unroll 4
    for (int i = lane; i < 128; i += 32) {
        float4 v = r4[i], a = s4[i], b = d4[i];
        ss += v.x * a.x + v.y * a.y + v.z * a.z + v.w * a.w;
        dd += v.x * b.x + v.y * b.y + v.z * b.z + v.w * b.w;
    }
#pragma unroll
    for (int off = 16; off; off >>= 1) {
        ss += __shfl_down_sync(0xffffffffu, ss, off);
        dd += __shfl_down_sync(0xffffffffu, dd, off);
    }
    if (lane == 0) { g_asrc1[gw] = ss; g_adst1[gw] = dd; }
}

// ---------------------------------------------------------------------------
// fused layer-1 softmax + aggregation: one block (256 thr) per destination.
// Exact segment max/sum (no atomics), head-mean folded into alpha.
// Each thread owns cols {2t, 2t+1} of the 512-wide output.
// ---------------------------------------------------------------------------
__global__ __launch_bounds__(256)
void k_agg1(int Nn) {
    const int d = blockIdx.x;
    const int tid = threadIdx.x, lane = tid & 31, warp = tid >> 5;
    const int beg = g_rowptr[d], end = g_rowptr[d + 1];

    __shared__ float4 rwarp[8];
    __shared__ float4 rbc;
    __shared__ int    ssrc[256];
    __shared__ float4 sal[256];

    float4 ad = *(const float4*)(g_adst1 + (size_t)d * 4);
    const float NEGINF = __int_as_float(0xff800000);

    // --- phase A: segment max ---
    float4 mx = make_float4(NEGINF, NEGINF, NEGINF, NEGINF);
    for (int j = beg + tid; j < end; j += 256) {
        int s = g_csr_src[j];
        float4 as = *(const float4*)(g_asrc1 + (size_t)s * 4);
        mx.x = fmaxf(mx.x, lrelu(as.x + ad.x));
        mx.y = fmaxf(mx.y, lrelu(as.y + ad.y));
        mx.z = fmaxf(mx.z, lrelu(as.z + ad.z));
        mx.w = fmaxf(mx.w, lrelu(as.w + ad.w));
    }
#pragma unroll
    for (int o = 16; o; o >>= 1) {
        mx.x = fmaxf(mx.x, __shfl_down_sync(0xffffffffu, mx.x, o));
        mx.y = fmaxf(mx.y, __shfl_down_sync(0xffffffffu, mx.y, o));
        mx.z = fmaxf(mx.z, __shfl_down_sync(0xffffffffu, mx.z, o));
        mx.w = fmaxf(mx.w, __shfl_down_sync(0xffffffffu, mx.w, o));
    }
    if (lane == 0) rwarp[warp] = mx;
    __syncthreads();
    if (tid == 0) {
        float4 m = rwarp[0];
#pragma unroll
        for (int w = 1; w < 8; w++) {
            m.x = fmaxf(m.x, rwarp[w].x); m.y = fmaxf(m.y, rwarp[w].y);
            m.z = fmaxf(m.z, rwarp[w].z); m.w = fmaxf(m.w, rwarp[w].w);
        }
        rbc = m;
    }
    __syncthreads();
    mx = rbc;

    // --- phase B: segment sum of exp ---
    float4 sm = make_float4(0.f, 0.f, 0.f, 0.f);
    for (int j = beg + tid; j < end; j += 256) {
        int s = g_csr_src[j];
        float4 as = *(const float4*)(g_asrc1 + (size_t)s * 4);
        sm.x += expf(lrelu(as.x + ad.x) - mx.x);
        sm.y += expf(lrelu(as.y + ad.y) - mx.y);
        sm.z += expf(lrelu(as.z + ad.z) - mx.z);
        sm.w += expf(lrelu(as.w + ad.w) - mx.w);
    }
#pragma unroll
    for (int o = 16; o; o >>= 1) {
        sm.x += __shfl_down_sync(0xffffffffu, sm.x, o);
        sm.y += __shfl_down_sync(0xffffffffu, sm.y, o);
        sm.z += __shfl_down_sync(0xffffffffu, sm.z, o);
        sm.w += __shfl_down_sync(0xffffffffu, sm.w, o);
    }
    if (lane == 0) rwarp[warp] = sm;
    __syncthreads();
    if (tid == 0) {
        float4 t = rwarp[0];
#pragma unroll
        for (int w = 1; w < 8; w++) {
            t.x += rwarp[w].x; t.y += rwarp[w].y; t.z += rwarp[w].z; t.w += rwarp[w].w;
        }
        rbc = t;
    }
    __syncthreads();
    sm = rbc;
    float4 inv;
    inv.x = 0.25f / (sm.x + 1e-16f);
    inv.y = 0.25f / (sm.y + 1e-16f);
    inv.z = 0.25f / (sm.z + 1e-16f);
    inv.w = 0.25f / (sm.w + 1e-16f);

    // --- phase C: chunked alpha + message accumulation ---
    float2 acc = make_float2(0.f, 0.f);
    for (int c0 = beg; c0 < end; c0 += 256) {
        int cnt = min(end - c0, 256);
        __syncthreads();
        if (tid < cnt) {
            int s = g_csr_src[c0 + tid];
            float4 as = *(const float4*)(g_asrc1 + (size_t)s * 4);
            float4 al;
            al.x = expf(lrelu(as.x + ad.x) - mx.x) * inv.x;
            al.y = expf(lrelu(as.y + ad.y) - mx.y) * inv.y;
            al.z = expf(lrelu(as.z + ad.z) - mx.z) * inv.z;
            al.w = expf(lrelu(as.w + ad.w) - mx.w) * inv.w;
            ssrc[tid] = s;
            sal[tid] = al;
        }
        __syncthreads();
        for (int jj = 0; jj < cnt; jj++) {
            const float* h = g_H1 + (size_t)ssrc[jj] * 2048 + 2 * tid;
            float4 al = sal[jj];
            float2 v0 = __ldg((const float2*)(h));
            float2 v1 = __ldg((const float2*)(h + 512));
            float2 v2 = __ldg((const float2*)(h + 1024));
            float2 v3 = __ldg((const float2*)(h + 1536));
            acc.x += al.x * v0.x + al.y * v1.x + al.z * v2.x + al.w * v3.x;
            acc.y += al.x * v0.y + al.y * v1.y + al.z * v2.y + al.w * v3.y;
        }
    }
    *(float2*)(g_out1 + (size_t)d * 512 + 2 * tid) = acc;
}

// ---------------------------------------------------------------------------
// BatchNorm stats (b1 BN-invariant -> skipped) + normalize + ELU
// ---------------------------------------------------------------------------
__global__ void k_bnstats(int Nn) {
    int c = blockIdx.x * blockDim.x + threadIdx.x;   // 0..511
    int r0 = blockIdx.y * 64;
    int r1 = min(r0 + 64, Nn);
    float s1 = 0.f, s2 = 0.f;
    for (int r = r0; r < r1; r++) {
        float v = g_out1[(size_t)r * 512 + c];
        s1 += v;
        s2 = fmaf(v, v, s2);
    }
    atomicAdd(&g_stats[c], s1);
    atomicAdd(&g_stats[512 + c], s2);
}

__global__ void k_bnelu(const float* __restrict__ gamma, const float* __restrict__ beta,
                        int Nn, float invN) {
    size_t total = (size_t)Nn * 512;
    for (size_t i = (size_t)blockIdx.x * blockDim.x + threadIdx.x; i < total;
         i += (size_t)gridDim.x * blockDim.x) {
        int c = (int)(i & 511);
        float mu = g_stats[c] * invN;
        float var = g_stats[512 + c] * invN - mu * mu;
        float x = (g_out1[i] - mu) * rsqrtf(var + 1e-5f) * gamma[c] + beta[c];
        g_hmid[i] = x > 0.f ? x : expm1f(x);
    }
}

// ---------------------------------------------------------------------------
// layer-2 prep: H2 = hmid @ W2 (one warp per row) + attention scalars
// ---------------------------------------------------------------------------
__global__ void k_l2prep(const float* __restrict__ W2, const float* __restrict__ as2,
                         const float* __restrict__ ad2, int Nn) {
    int gw = (int)(((size_t)blockIdx.x * blockDim.x + threadIdx.x) >> 5);
    int lane = threadIdx.x & 31;
    if (gw >= Nn) return;
    const float* h = g_hmid + (size_t)gw * 512;
    float acc = 0.f;
    for (int kb = 0; kb < 16; kb++) {
        float hv = h[kb * 32 + lane];
#pragma unroll
        for (int j = 0; j < 32; j++) {
            float hk = __shfl_sync(0xffffffffu, hv, j);
            float w = (lane < 30) ? __ldg(W2 + (size_t)(kb * 32 + j) * 30 + lane) : 0.f;
            acc = fmaf(hk, w, acc);
        }
    }
    float sa = (lane < 30) ? acc * __ldg(as2 + lane) : 0.f;
    float sd = (lane < 30) ? acc * __ldg(ad2 + lane) : 0.f;
#pragma unroll
    for (int off = 16; off; off >>= 1) {
        sa += __shfl_down_sync(0xffffffffu, sa, off);
        sd += __shfl_down_sync(0xffffffffu, sd, off);
    }
    if (lane < 30) g_H2[(size_t)gw * 30 + lane] = acc;
    if (lane == 0) { g_asrc2[gw] = sa; g_adst2[gw] = sd; }
}

// ---------------------------------------------------------------------------
// layer-2 edge passes (H=1, C=30) — unchanged atomic path (cheap)
// ---------------------------------------------------------------------------
__global__ void k_edge_max2(const int* __restrict__ ei, int E, int Nn) {
    int e = blockIdx.x * blockDim.x + threadIdx.x;
    if (e >= E + Nn) return;
    int s, d;
    if (e < E) { s = ei[e]; d = ei[E + e]; } else { s = d = e - E; }
    float v = lrelu(g_asrc2[s] + g_adst2[d]);
    g_e2[e] = v;
    atomicMax(&g_max2[d], f2ord(v));
}

__global__ void k_exp2(const int* __restrict__ ei, int E, int Nn) {
    int e = blockIdx.x * blockDim.x + threadIdx.x;
    if (e >= E + Nn) return;
    int d = (e < E) ? ei[E + e] : e - E;
    float ex = expf(g_e2[e] - ord2f(g_max2[d]));
    g_e2[e] = ex;
    atomicAdd(&g_sum2[d], ex);
}

__global__ void k_msg2(const int* __restrict__ ei, int E, int Nn, float* __restrict__ out) {
    int gw = (int)(((size_t)blockIdx.x * blockDim.x + threadIdx.x) >> 5);
    int lane = threadIdx.x & 31;
    if (gw >= E + Nn) return;
    int s, d;
    if (gw < E) { s = ei[gw]; d = ei[E + gw]; } else { s = d = gw - E; }
    float al = g_e2[gw] / (g_sum2[d] + 1e-16f);
    if (lane < 30)
        atomicAdd(out + (size_t)d * 30 + lane, al * __ldg(g_H2 + (size_t)s * 30 + lane));
}

// ---------------------------------------------------------------------------
// launch
// ---------------------------------------------------------------------------
extern "C" void kernel_launch(void* const* d_in, const int* in_sizes, int n_in,
                              void* d_out, int out_size) {
    const float* x       = (const float*)d_in[0];
    const int*   ei      = (const int*)d_in[1];
    const float* W1      = (const float*)d_in[2];
    const float* attsrc1 = (const float*)d_in[3];
    const float* attdst1 = (const float*)d_in[4];
    // d_in[5] = b1: BN-invariant, skipped
    const float* gamma   = (const float*)d_in[6];
    const float* beta    = (const float*)d_in[7];
    const float* W2      = (const float*)d_in[8];
    const float* attsrc2 = (const float*)d_in[9];
    const float* attdst2 = (const float*)d_in[10];
    const float* b2      = (const float*)d_in[11];
    float* out = (float*)d_out;

    int Nn = in_sizes[0] / 2000;
    int E  = in_sizes[1] / 2;
    int Etot = E + Nn;
    int eb = (Etot + 255) / 256;

    cudaFuncSetAttribute(k_gemm1, cudaFuncAttributeMaxDynamicSharedMemorySize, SMEM_GEMM);

    k_init<<<2048, 256>>>(out, b2, Nn);
    k_deg<<<eb, 256>>>(ei, E, Nn);
    k_scan<<<1, 1024>>>(Nn);
    k_scatter<<<eb, 256>>>(ei, E, Nn);

    dim3 g1(2048 / 128, (Nn + 127) / 128);
    k_gemm1<<<g1, 256, SMEM_GEMM>>>(x, W1, Nn);

    k_att1<<<(Nn * 4 * 32 + 255) / 256, 256>>>(attsrc1, attdst1, Nn);

    k_agg1<<<Nn, 256>>>(Nn);

    dim3 gs(2, (Nn + 63) / 64);
    k_bnstats<<<gs, 256>>>(Nn);
    k_bnelu<<<4096, 256>>>(gamma, beta, Nn, 1.f / (float)Nn);

    k_l2prep<<<(int)(((size_t)Nn * 32 + 255) / 256), 256>>>(W2, attsrc2, attdst2, Nn);

    k_edge_max2<<<eb, 256>>>(ei, E, Nn);
    k_exp2<<<eb, 256>>>(ei, E, Nn);
    int mb = (int)(((size_t)Etot * 32 + 255) / 256);
    k_msg2<<<mb, 256>>>(ei, E, Nn, out);
}